// round 6
// baseline (speedup 1.0000x reference)
#include <cuda_runtime.h>
#include <math_constants.h>

#define BSZ   64
#define NGEN  128
#define NCLS  30
#define SEQ   2048
#define G     16
#define TGOLD (BSZ * G)                              // 1024
#define COST_ELEMS ((size_t)BSZ * NGEN * TGOLD)      // 8388608
#define NCOST_BLOCKS (BSZ * NGEN)                    // 8192

struct Ptrs {
    const float* pos[8];   // 8 positional logit tensors [BSZ*NGEN, SEQ]
    const int*   gidx[8];  // 8 gold index arrays [TGOLD]
};

__device__ int g_cnt[BSZ];   // per-example completed cost-row counter

__global__ void init_kernel() {
    if (threadIdx.x < BSZ) g_cnt[threadIdx.x] = 0;
}

// ---------------------------------------------------------------------------
// f32 monotone key helpers + redux.min
// ---------------------------------------------------------------------------
__device__ __forceinline__ unsigned fkey(float x) {
    int b = __float_as_int(x);
    return (unsigned)(b ^ ((b >> 31) | 0x80000000));
}
__device__ __forceinline__ float funkey(unsigned k) {
    int b = (k & 0x80000000u) ? (int)(k ^ 0x80000000u) : (int)(~k);
    return __int_as_float(b);
}
__device__ __forceinline__ unsigned redux_min_u32(unsigned x) {
    unsigned r;
    asm volatile("redux.sync.min.u32 %0, %1, 0xffffffff;" : "=r"(r) : "r"(x));
    return r;
}

// ---------------------------------------------------------------------------
// Fused kernel.
//  bid <  8192 : cost role — one (b,n) row, 256 threads, double-buffered
//                probs, ONE barrier/dist, prefetch across dists (identical
//                arithmetic to the R5 cost kernel -> bit-identical output).
//                On completion: threadfence + atomicAdd(g_cnt[example]).
//  bid >= 8192 : lsa role — warp 0 spins until its example's 128 cost rows
//                are done, then solves LAPJV (f32, register-resident
//                v/y/pred, 2-redux argmin). Unique-optimum => identical
//                assignment to the f64 reference.
// ---------------------------------------------------------------------------
__global__ __launch_bounds__(256)
void fused_kernel(const float* __restrict__ prel, const int* __restrict__ grel,
                  Ptrs ptrs, float* __restrict__ out) {
    __shared__ __align__(16) char smem_raw[16576];

    if (blockIdx.x < NCOST_BLOCKS) {
        // ================= cost role =================
        float (*probs)[SEQ] = (float (*)[SEQ])smem_raw;            // 16 KB
        float* relp = (float*)(smem_raw + 16384);                  // 120 B
        float (*red)[8] = (float (*)[8])(smem_raw + 16504);        // 64 B

        const int row = blockIdx.x;
        const int tid = threadIdx.x;
        const int w   = tid >> 5;
        const int lane = tid & 31;

        const float4* r4 = (const float4*)(ptrs.pos[0] + (size_t)row * SEQ);
        float4 v0 = r4[tid];
        float4 v1 = r4[tid + 256];

        if (tid < 32) {
            float e = (lane < NCLS) ? __expf(prel[(size_t)row * NCLS + lane]) : 0.f;
            float s = e;
            #pragma unroll
            for (int o = 16; o; o >>= 1) s += __shfl_xor_sync(0xffffffffu, s, o);
            if (lane < NCLS) relp[lane] = e / s;
        }
        __syncthreads();

        float acc0 = relp[grel[tid]];
        float acc1 = relp[grel[tid + 256]];
        float acc2 = relp[grel[tid + 512]];
        float acc3 = relp[grel[tid + 768]];

        #pragma unroll
        for (int d = 0; d < 8; d++) {
            const int pb = d & 1;
            float4 n0, n1;
            if (d < 7) {
                const float4* nx = (const float4*)(ptrs.pos[d + 1] + (size_t)row * SEQ);
                n0 = nx[tid]; n1 = nx[tid + 256];
            }
            const int* __restrict__ gi = ptrs.gidx[d];
            int g0 = gi[tid], g1 = gi[tid + 256], g2 = gi[tid + 512], g3 = gi[tid + 768];

            float4 e0, e1;
            e0.x = __expf(v0.x); e0.y = __expf(v0.y); e0.z = __expf(v0.z); e0.w = __expf(v0.w);
            e1.x = __expf(v1.x); e1.y = __expf(v1.y); e1.z = __expf(v1.z); e1.w = __expf(v1.w);
            ((float4*)probs[pb])[tid]       = e0;
            ((float4*)probs[pb])[tid + 256] = e1;

            float lsum = (e0.x + e0.y) + (e0.z + e0.w) + (e1.x + e1.y) + (e1.z + e1.w);
            #pragma unroll
            for (int o = 16; o; o >>= 1) lsum += __shfl_xor_sync(0xffffffffu, lsum, o);
            if (lane == 0) red[pb][w] = lsum;
            __syncthreads();                 // probs[pb] + red[pb] visible

            float s = ((red[pb][0] + red[pb][1]) + (red[pb][2] + red[pb][3]))
                    + ((red[pb][4] + red[pb][5]) + (red[pb][6] + red[pb][7]));
            float inv = 1.0f / s;

            acc0 += probs[pb][g0] * inv;
            acc1 += probs[pb][g1] * inv;
            acc2 += probs[pb][g2] * inv;
            acc3 += probs[pb][g3] * inv;
            // next dist writes the OTHER buffer; overwrite of this one is
            // ordered behind barrier d+1.
            v0 = n0; v1 = n1;
        }

        const size_t base = (size_t)row * TGOLD;
        out[base + tid]       = -acc0;
        out[base + tid + 256] = -acc1;
        out[base + tid + 512] = -acc2;
        out[base + tid + 768] = -acc3;

        __threadfence();
        __syncthreads();
        if (tid == 0) atomicAdd(&g_cnt[row >> 7], 1);

    } else {
        // ================= lsa role =================
        if (threadIdx.x >= 32) return;
        const int b = blockIdx.x - NCOST_BLOCKS;
        const int lane = threadIdx.x;

        float* Cf = (float*)smem_raw;                 // 8 KB
        int*   x  = (int*)(smem_raw + 8192);          // 64 B (row -> col)

        // wait for all 128 cost rows of example b
        if (lane == 0) {
            while (atomicAdd(&g_cnt[b], 0) < NGEN) __nanosleep(128);
        }
        __syncwarp();
        __threadfence();

        const float* cost = out;
        for (int j = lane; j < NGEN; j += 32) {
            const float4* src = (const float4*)(cost + ((size_t)(b * NGEN + j)) * TGOLD + b * G);
            #pragma unroll
            for (int q = 0; q < 4; q++) {
                float4 f = src[q];
                Cf[(q * 4 + 0) * NGEN + j] = f.x;
                Cf[(q * 4 + 1) * NGEN + j] = f.y;
                Cf[(q * 4 + 2) * NGEN + j] = f.z;
                Cf[(q * 4 + 3) * NGEN + j] = f.w;
            }
        }
        __syncwarp();

        float vreg[4];                 // v[j], j = lane + 32*t (ZERO init:
        int   yreg[4];                 //   rectangular dual feasibility)
        #pragma unroll
        for (int t = 0; t < 4; t++) { vreg[t] = 0.f; yreg[t] = -1; }

        for (int f = 0; f < G; f++) {
            float dreg[4];
            int   pr[4];
            #pragma unroll
            for (int t = 0; t < 4; t++) {
                dreg[t] = Cf[f * NGEN + lane + 32 * t] - vreg[t];
                pr[t] = f;
            }
            unsigned scan = 0;
            int jmin;
            float mu;

            while (true) {
                // per-lane best among unscanned (ascending j: < keeps min j)
                unsigned bestk = 0xFFFFFFFFu;
                unsigned bestj = 0xFFFFFFFFu;
                #pragma unroll
                for (int t = 0; t < 4; t++) {
                    if (!((scan >> t) & 1u)) {
                        unsigned k = fkey(dreg[t]);
                        if (k < bestk) { bestk = k; bestj = (unsigned)(lane + 32 * t); }
                    }
                }
                unsigned kmin = redux_min_u32(bestk);
                unsigned j1   = redux_min_u32((bestk == kmin) ? bestj : 0xFFFFFFFFu);
                mu   = funkey(kmin);
                jmin = (int)j1;

                const int tt = jmin >> 5, sl = jmin & 31;
                if (sl == lane) scan |= 1u << tt;

                // y[jmin], v[jmin] via register select + shfl
                int   ysel = (tt == 0) ? yreg[0] : (tt == 1) ? yreg[1]
                           : (tt == 2) ? yreg[2] : yreg[3];
                float vsel = (tt == 0) ? vreg[0] : (tt == 1) ? vreg[1]
                           : (tt == 2) ? vreg[2] : vreg[3];
                int   i1 = __shfl_sync(0xffffffffu, ysel, sl);
                float vj = __shfl_sync(0xffffffffu, vsel, sl);
                if (i1 < 0) break;

                float ui = Cf[i1 * NGEN + jmin] - vj;

                #pragma unroll
                for (int t = 0; t < 4; t++) {
                    if (!((scan >> t) & 1u)) {
                        int j = lane + 32 * t;
                        float nd = mu + (Cf[i1 * NGEN + j] - vreg[t]) - ui;
                        if (nd < dreg[t]) { dreg[t] = nd; pr[t] = i1; }
                    }
                }
            }

            // deferred potential update over scanned columns
            #pragma unroll
            for (int t = 0; t < 4; t++)
                if ((scan >> t) & 1u) vreg[t] += dreg[t] - mu;

            // augment along pred chain
            int j = jmin;
            while (true) {
                const int tt = j >> 5, sl = j & 31;
                int psel = (tt == 0) ? pr[0] : (tt == 1) ? pr[1]
                         : (tt == 2) ? pr[2] : pr[3];
                int i = __shfl_sync(0xffffffffu, psel, sl);
                if ((j & 31) == lane) yreg[j >> 5] = i;   // y[j] = i
                int jn = 0;
                if (lane == 0) {
                    jn = (i == f) ? -1 : x[i];
                    x[i] = j;
                }
                jn = __shfl_sync(0xffffffffu, jn, 0);
                if (i == f) break;
                j = jn;
            }
            __syncwarp();
        }

        // transposed return: col[i] = x[i]; order = argsort(col)
        __syncwarp();
        if (lane < G) {
            float* rows_out = (float*)(out + COST_ELEMS);
            float* cols_out = rows_out + (size_t)BSZ * G;
            int c = x[lane];
            int rank = 0;
            #pragma unroll
            for (int r2 = 0; r2 < G; r2++) rank += (x[r2] < c) ? 1 : 0;
            rows_out[b * G + rank] = (float)c;
            cols_out[b * G + rank] = (float)lane;
        }
    }
}

// ---------------------------------------------------------------------------
// Launch
// ---------------------------------------------------------------------------
extern "C" void kernel_launch(void* const* d_in, const int* in_sizes, int n_in,
                              void* d_out, int out_size) {
    const float* prel = (const float*)d_in[0];
    Ptrs ptrs;
    for (int d = 0; d < 8; d++) ptrs.pos[d]  = (const float*)d_in[1 + d];
    const int* grel = (const int*)d_in[9];
    for (int d = 0; d < 8; d++) ptrs.gidx[d] = (const int*)d_in[10 + d];

    float* out = (float*)d_out;

    init_kernel<<<1, 64>>>();
    fused_kernel<<<NCOST_BLOCKS + BSZ, 256>>>(prel, grel, ptrs, out);
}

// round 7
// speedup vs baseline: 1.1752x; 1.1752x over previous
#include <cuda_runtime.h>
#include <math_constants.h>

#define BSZ   64
#define NGEN  128
#define NCLS  30
#define SEQ   2048
#define G     16
#define TGOLD (BSZ * G)                              // 1024
#define COST_ELEMS ((size_t)BSZ * NGEN * TGOLD)      // 8388608

struct Ptrs {
    const float* pos[8];   // 8 positional logit tensors [BSZ*NGEN, SEQ]
    const int*   gidx[8];  // 8 gold index arrays [TGOLD]
};

// ---------------------------------------------------------------------------
// cp.async helpers
// ---------------------------------------------------------------------------
__device__ __forceinline__ unsigned smem_u32(const void* p) {
    unsigned a;
    asm("{ .reg .u64 t; cvta.to.shared.u64 t, %1; cvt.u32.u64 %0, t; }"
        : "=r"(a) : "l"(p));
    return a;
}
__device__ __forceinline__ void cp_async16(unsigned dst, const float* src) {
    asm volatile("cp.async.cg.shared.global [%0], [%1], 16;" :: "r"(dst), "l"(src));
}

// ---------------------------------------------------------------------------
// Cost kernel: one block per (b,n) row, 256 threads.
// Depth-3 cp.async pipeline over 4 smem stages; exp in-place in the stage
// (each thread touches only its own staged elements, so wait_group is enough
// before the exp phase); ONE __syncthreads per distribution; red
// double-buffered by parity. Arithmetic identical to R5 (bit-identical out).
// ---------------------------------------------------------------------------
__global__ __launch_bounds__(256)
void cost_kernel(const float* __restrict__ prel, const int* __restrict__ grel,
                 Ptrs ptrs, float* __restrict__ out) {
    const int row = blockIdx.x;
    const int tid = threadIdx.x;
    const int w   = tid >> 5;
    const int lane = tid & 31;

    __shared__ float stage[4][SEQ];       // 32 KB
    __shared__ float relp[NCLS];
    __shared__ float red[2][8];

    const unsigned sbase = smem_u32(&stage[0][0]);

    // prologue: dists 0..2 in flight
    #pragma unroll
    for (int d = 0; d < 3; d++) {
        const float* src = ptrs.pos[d] + (size_t)row * SEQ;
        unsigned dst = sbase + (unsigned)(d * (SEQ * 4)) + (unsigned)(tid * 16);
        cp_async16(dst, src + 4 * tid);
        cp_async16(dst + 4096, src + 1024 + 4 * tid);
        asm volatile("cp.async.commit_group;");
    }

    // rel-class softmax (warp 0) overlaps the async loads
    if (tid < 32) {
        float e = (lane < NCLS) ? __expf(prel[(size_t)row * NCLS + lane]) : 0.f;
        float s = e;
        #pragma unroll
        for (int o = 16; o; o >>= 1) s += __shfl_xor_sync(0xffffffffu, s, o);
        if (lane < NCLS) relp[lane] = e / s;
    }
    __syncthreads();

    float acc0 = relp[grel[tid]];
    float acc1 = relp[grel[tid + 256]];
    float acc2 = relp[grel[tid + 512]];
    float acc3 = relp[grel[tid + 768]];

    #pragma unroll
    for (int d = 0; d < 8; d++) {
        const int sb = d & 3;
        const int pb = d & 1;

        // wait for MY copies of dist d (allow d+1, d+2 still pending)
        if (d <= 5)      asm volatile("cp.async.wait_group 2;");
        else if (d == 6) asm volatile("cp.async.wait_group 1;");
        else             asm volatile("cp.async.wait_group 0;");

        // issue gather-index loads early (L2-resident)
        const int* __restrict__ gi = ptrs.gidx[d];
        int g0 = gi[tid], g1 = gi[tid + 256], g2 = gi[tid + 512], g3 = gi[tid + 768];

        // exp in place on this thread's own staged elements
        float4* sp = (float4*)&stage[sb][0];
        float4 e0 = sp[tid];
        float4 e1 = sp[tid + 256];
        e0.x = __expf(e0.x); e0.y = __expf(e0.y); e0.z = __expf(e0.z); e0.w = __expf(e0.w);
        e1.x = __expf(e1.x); e1.y = __expf(e1.y); e1.z = __expf(e1.z); e1.w = __expf(e1.w);
        sp[tid]       = e0;
        sp[tid + 256] = e1;

        float lsum = (e0.x + e0.y) + (e0.z + e0.w) + (e1.x + e1.y) + (e1.z + e1.w);
        #pragma unroll
        for (int o = 16; o; o >>= 1) lsum += __shfl_xor_sync(0xffffffffu, lsum, o);
        if (lane == 0) red[pb][w] = lsum;
        __syncthreads();                  // probs + red visible; also orders
                                          // the d+3 issue below behind all
                                          // gathers of dist d-1 (same buffer)

        float s = ((red[pb][0] + red[pb][1]) + (red[pb][2] + red[pb][3]))
                + ((red[pb][4] + red[pb][5]) + (red[pb][6] + red[pb][7]));
        float inv = 1.0f / s;

        acc0 += stage[sb][g0] * inv;
        acc1 += stage[sb][g1] * inv;
        acc2 += stage[sb][g2] * inv;
        acc3 += stage[sb][g3] * inv;

        // refill: dist d+3 into stage (d+3)&3 == (d-1)&3
        if (d + 3 < 8) {
            const float* src = ptrs.pos[d + 3] + (size_t)row * SEQ;
            unsigned dst = sbase + (unsigned)(((d + 3) & 3) * (SEQ * 4))
                                 + (unsigned)(tid * 16);
            cp_async16(dst, src + 4 * tid);
            cp_async16(dst + 4096, src + 1024 + 4 * tid);
            asm volatile("cp.async.commit_group;");
        }
    }

    const size_t base = (size_t)row * TGOLD;
    out[base + tid]       = -acc0;
    out[base + tid + 256] = -acc1;
    out[base + tid + 512] = -acc2;
    out[base + tid + 768] = -acc3;
}

// ---------------------------------------------------------------------------
// f32 monotone key + redux.min
// ---------------------------------------------------------------------------
__device__ __forceinline__ unsigned fkey(float x) {
    int b = __float_as_int(x);
    return (unsigned)(b ^ ((b >> 31) | 0x80000000));
}
__device__ __forceinline__ float funkey(unsigned k) {
    int b = (k & 0x80000000u) ? (int)(k ^ 0x80000000u) : (int)(~k);
    return __int_as_float(b);
}
__device__ __forceinline__ unsigned redux_min_u32(unsigned x) {
    unsigned r;
    asm volatile("redux.sync.min.u32 %0, %1, 0xffffffff;" : "=r"(r) : "r"(x));
    return r;
}

// ---------------------------------------------------------------------------
// LSA: one warp per example. LAPJV shortest augmenting path, f32,
// register-resident dist/pred/v/y (validated in R6: identical assignment to
// the f64 reference — unique LP optimum, competing-path gaps >> f32 eps).
// v zero-init -> rectangular dual feasibility. Argmin: monotone u32 key +
// 2x redux.min with smallest-j tie-break (np.argmin semantics).
// C[i][j] = cost[b, j, b*G + i]  (16 x 128 transposed view).
// ---------------------------------------------------------------------------
__global__ __launch_bounds__(32)
void lsa_kernel(const float* __restrict__ cost, float* __restrict__ rows_out,
                float* __restrict__ cols_out) {
    const int b = blockIdx.x;
    const int lane = threadIdx.x;

    __shared__ float Cf[G * NGEN];   // 8 KB
    __shared__ int   x[G];           // row -> col

    for (int j = lane; j < NGEN; j += 32) {
        const float4* src = (const float4*)(cost + ((size_t)(b * NGEN + j)) * TGOLD + b * G);
        #pragma unroll
        for (int q = 0; q < 4; q++) {
            float4 f = src[q];
            Cf[(q * 4 + 0) * NGEN + j] = f.x;
            Cf[(q * 4 + 1) * NGEN + j] = f.y;
            Cf[(q * 4 + 2) * NGEN + j] = f.z;
            Cf[(q * 4 + 3) * NGEN + j] = f.w;
        }
    }
    __syncwarp();

    float vreg[4];                 // v[j], j = lane + 32*t (ZERO init)
    int   yreg[4];                 // col -> row (-1 free)
    #pragma unroll
    for (int t = 0; t < 4; t++) { vreg[t] = 0.f; yreg[t] = -1; }

    for (int f = 0; f < G; f++) {
        float dreg[4];
        int   pr[4];
        #pragma unroll
        for (int t = 0; t < 4; t++) {
            dreg[t] = Cf[f * NGEN + lane + 32 * t] - vreg[t];
            pr[t] = f;
        }
        unsigned scan = 0;
        int jmin;
        float mu;

        while (true) {
            unsigned bestk = 0xFFFFFFFFu;
            unsigned bestj = 0xFFFFFFFFu;
            #pragma unroll
            for (int t = 0; t < 4; t++) {
                if (!((scan >> t) & 1u)) {
                    unsigned k = fkey(dreg[t]);
                    if (k < bestk) { bestk = k; bestj = (unsigned)(lane + 32 * t); }
                }
            }
            unsigned kmin = redux_min_u32(bestk);
            unsigned j1   = redux_min_u32((bestk == kmin) ? bestj : 0xFFFFFFFFu);
            mu   = funkey(kmin);
            jmin = (int)j1;

            const int tt = jmin >> 5, sl = jmin & 31;
            if (sl == lane) scan |= 1u << tt;

            int   ysel = (tt == 0) ? yreg[0] : (tt == 1) ? yreg[1]
                       : (tt == 2) ? yreg[2] : yreg[3];
            float vsel = (tt == 0) ? vreg[0] : (tt == 1) ? vreg[1]
                       : (tt == 2) ? vreg[2] : vreg[3];
            int   i1 = __shfl_sync(0xffffffffu, ysel, sl);
            float vj = __shfl_sync(0xffffffffu, vsel, sl);
            if (i1 < 0) break;

            float ui = Cf[i1 * NGEN + jmin] - vj;

            #pragma unroll
            for (int t = 0; t < 4; t++) {
                if (!((scan >> t) & 1u)) {
                    int j = lane + 32 * t;
                    float nd = mu + (Cf[i1 * NGEN + j] - vreg[t]) - ui;
                    if (nd < dreg[t]) { dreg[t] = nd; pr[t] = i1; }
                }
            }
        }

        // deferred potential update over scanned columns
        #pragma unroll
        for (int t = 0; t < 4; t++)
            if ((scan >> t) & 1u) vreg[t] += dreg[t] - mu;

        // augment along pred chain
        int j = jmin;
        while (true) {
            const int tt = j >> 5, sl = j & 31;
            int psel = (tt == 0) ? pr[0] : (tt == 1) ? pr[1]
                     : (tt == 2) ? pr[2] : pr[3];
            int i = __shfl_sync(0xffffffffu, psel, sl);
            if ((j & 31) == lane) yreg[j >> 5] = i;   // y[j] = i
            int jn = 0;
            if (lane == 0) {
                jn = (i == f) ? -1 : x[i];
                x[i] = j;
            }
            jn = __shfl_sync(0xffffffffu, jn, 0);
            if (i == f) break;
            j = jn;
        }
        __syncwarp();
    }

    // transposed return: col[i] = x[i]; order = argsort(col)
    if (lane < G) {
        int c = x[lane];
        int rank = 0;
        #pragma unroll
        for (int r2 = 0; r2 < G; r2++) rank += (x[r2] < c) ? 1 : 0;
        rows_out[b * G + rank] = (float)c;
        cols_out[b * G + rank] = (float)lane;
    }
}

// ---------------------------------------------------------------------------
// Launch
// ---------------------------------------------------------------------------
extern "C" void kernel_launch(void* const* d_in, const int* in_sizes, int n_in,
                              void* d_out, int out_size) {
    const float* prel = (const float*)d_in[0];
    Ptrs ptrs;
    for (int d = 0; d < 8; d++) ptrs.pos[d]  = (const float*)d_in[1 + d];
    const int* grel = (const int*)d_in[9];
    for (int d = 0; d < 8; d++) ptrs.gidx[d] = (const int*)d_in[10 + d];

    float* out = (float*)d_out;

    cost_kernel<<<BSZ * NGEN, 256>>>(prel, grel, ptrs, out);

    float* rows_out = out + COST_ELEMS;
    float* cols_out = rows_out + (size_t)BSZ * G;
    lsa_kernel<<<BSZ, 32>>>(out, rows_out, cols_out);
}

// round 8
// speedup vs baseline: 1.2838x; 1.0924x over previous
#include <cuda_runtime.h>
#include <math_constants.h>

#define BSZ   64
#define NGEN  128
#define NCLS  30
#define SEQ   2048
#define G     16
#define TGOLD (BSZ * G)                              // 1024
#define COST_ELEMS ((size_t)BSZ * NGEN * TGOLD)      // 8388608

struct Ptrs {
    const float* pos[8];   // 8 positional logit tensors [BSZ*NGEN, SEQ]
    const int*   gidx[8];  // 8 gold index arrays [TGOLD]
};

// ---------------------------------------------------------------------------
// cp.async helpers
// ---------------------------------------------------------------------------
__device__ __forceinline__ unsigned smem_u32(const void* p) {
    unsigned a;
    asm("{ .reg .u64 t; cvta.to.shared.u64 t, %1; cvt.u32.u64 %0, t; }"
        : "=r"(a) : "l"(p));
    return a;
}
__device__ __forceinline__ void cp_async16(unsigned dst, const float* src) {
    asm volatile("cp.async.cg.shared.global [%0], [%1], 16;" :: "r"(dst), "l"(src));
}

// ---------------------------------------------------------------------------
// Cost kernel: one block per (b,n) row, 256 threads.
// Depth-3 cp.async pipeline over 4 smem stages holding RAW logits.
// Sum phase reads only the thread's own staged bytes (per-thread wait_group
// is sufficient); ONE __syncthreads per dist publishes all cp.asyncs before
// the cross-thread gather; probs are NEVER stored — gather reads raw logits
// and applies __expf at the use site (bit-identical result, no STS).
// Thread owns gold cols 4*tid..4*tid+3: int4 index loads, STG.128 output.
// ---------------------------------------------------------------------------
__global__ __launch_bounds__(256)
void cost_kernel(const float* __restrict__ prel, const int* __restrict__ grel,
                 Ptrs ptrs, float* __restrict__ out) {
    const int row = blockIdx.x;
    const int tid = threadIdx.x;
    const int w   = tid >> 5;
    const int lane = tid & 31;

    __shared__ float stage[4][SEQ];       // 32 KB (raw logits)
    __shared__ float relp[NCLS];
    __shared__ float red[2][8];

    const unsigned sbase = smem_u32(&stage[0][0]);

    // prologue: dists 0..2 in flight
    #pragma unroll
    for (int d = 0; d < 3; d++) {
        const float* src = ptrs.pos[d] + (size_t)row * SEQ;
        unsigned dst = sbase + (unsigned)(d * (SEQ * 4)) + (unsigned)(tid * 16);
        cp_async16(dst, src + 4 * tid);
        cp_async16(dst + 4096, src + 1024 + 4 * tid);
        asm volatile("cp.async.commit_group;");
    }

    // rel-class softmax (warp 0) overlaps the async loads
    if (tid < 32) {
        float e = (lane < NCLS) ? __expf(prel[(size_t)row * NCLS + lane]) : 0.f;
        float s = e;
        #pragma unroll
        for (int o = 16; o; o >>= 1) s += __shfl_xor_sync(0xffffffffu, s, o);
        if (lane < NCLS) relp[lane] = e / s;
    }
    __syncthreads();

    const int4 gr = ((const int4*)grel)[tid];
    float acc0 = relp[gr.x];
    float acc1 = relp[gr.y];
    float acc2 = relp[gr.z];
    float acc3 = relp[gr.w];

    #pragma unroll
    for (int d = 0; d < 8; d++) {
        const int sb = d & 3;
        const int pb = d & 1;

        // wait for MY copies of dist d (d+1, d+2 may still be in flight)
        if (d <= 5)      asm volatile("cp.async.wait_group 2;");
        else if (d == 6) asm volatile("cp.async.wait_group 1;");
        else             asm volatile("cp.async.wait_group 0;");

        // gather indices for this dist (single int4, L2-resident)
        const int4 gi = ((const int4*)ptrs.gidx[d])[tid];

        // sum of exps over this thread's own staged elements (raw kept!)
        const float4* sp = (const float4*)&stage[sb][0];
        float4 x0 = sp[tid];
        float4 x1 = sp[tid + 256];
        float e00 = __expf(x0.x), e01 = __expf(x0.y),
              e02 = __expf(x0.z), e03 = __expf(x0.w);
        float e10 = __expf(x1.x), e11 = __expf(x1.y),
              e12 = __expf(x1.z), e13 = __expf(x1.w);
        float lsum = (e00 + e01) + (e02 + e03) + (e10 + e11) + (e12 + e13);
        #pragma unroll
        for (int o = 16; o; o >>= 1) lsum += __shfl_xor_sync(0xffffffffu, lsum, o);
        if (lane == 0) red[pb][w] = lsum;
        __syncthreads();     // (a) red visible  (b) ALL threads' cp.asyncs of
                             // dist d complete  (c) gathers of d-1 ordered
                             // before the d+3 refill below

        float s = ((red[pb][0] + red[pb][1]) + (red[pb][2] + red[pb][3]))
                + ((red[pb][4] + red[pb][5]) + (red[pb][6] + red[pb][7]));
        float inv = 1.0f / s;

        // gather raw logits, exp at use site (same bits as stored probs)
        acc0 += __expf(stage[sb][gi.x]) * inv;
        acc1 += __expf(stage[sb][gi.y]) * inv;
        acc2 += __expf(stage[sb][gi.z]) * inv;
        acc3 += __expf(stage[sb][gi.w]) * inv;

        // refill: dist d+3 into stage (d+3)&3 == (d-1)&3
        if (d + 3 < 8) {
            const float* src = ptrs.pos[d + 3] + (size_t)row * SEQ;
            unsigned dst = sbase + (unsigned)(((d + 3) & 3) * (SEQ * 4))
                                 + (unsigned)(tid * 16);
            cp_async16(dst, src + 4 * tid);
            cp_async16(dst + 4096, src + 1024 + 4 * tid);
            asm volatile("cp.async.commit_group;");
        }
    }

    float4 res = make_float4(-acc0, -acc1, -acc2, -acc3);
    ((float4*)(out + (size_t)row * TGOLD))[tid] = res;
}

// ---------------------------------------------------------------------------
// f32 monotone key + redux.min
// ---------------------------------------------------------------------------
__device__ __forceinline__ unsigned fkey(float x) {
    int b = __float_as_int(x);
    return (unsigned)(b ^ ((b >> 31) | 0x80000000));
}
__device__ __forceinline__ float funkey(unsigned k) {
    int b = (k & 0x80000000u) ? (int)(k ^ 0x80000000u) : (int)(~k);
    return __int_as_float(b);
}
__device__ __forceinline__ unsigned redux_min_u32(unsigned x) {
    unsigned r;
    asm volatile("redux.sync.min.u32 %0, %1, 0xffffffff;" : "=r"(r) : "r"(x));
    return r;
}

// ---------------------------------------------------------------------------
// LSA: one warp per example. LAPJV shortest augmenting path, f32,
// register-resident dist/pred/v/y (validated: identical assignment to the
// f64 reference — unique LP optimum). v zero-init -> rectangular dual
// feasibility. Argmin: monotone u32 key + 2x redux.min, smallest-j ties.
// C[i][j] = cost[b, j, b*G + i]  (16 x 128 transposed view).
// ---------------------------------------------------------------------------
__global__ __launch_bounds__(32)
void lsa_kernel(const float* __restrict__ cost, float* __restrict__ rows_out,
                float* __restrict__ cols_out) {
    const int b = blockIdx.x;
    const int lane = threadIdx.x;

    __shared__ float Cf[G * NGEN];   // 8 KB
    __shared__ int   x[G];           // row -> col

    for (int j = lane; j < NGEN; j += 32) {
        const float4* src = (const float4*)(cost + ((size_t)(b * NGEN + j)) * TGOLD + b * G);
        #pragma unroll
        for (int q = 0; q < 4; q++) {
            float4 f = src[q];
            Cf[(q * 4 + 0) * NGEN + j] = f.x;
            Cf[(q * 4 + 1) * NGEN + j] = f.y;
            Cf[(q * 4 + 2) * NGEN + j] = f.z;
            Cf[(q * 4 + 3) * NGEN + j] = f.w;
        }
    }
    __syncwarp();

    float vreg[4];                 // v[j], j = lane + 32*t (ZERO init)
    int   yreg[4];                 // col -> row (-1 free)
    #pragma unroll
    for (int t = 0; t < 4; t++) { vreg[t] = 0.f; yreg[t] = -1; }

    for (int f = 0; f < G; f++) {
        float dreg[4];
        int   pr[4];
        #pragma unroll
        for (int t = 0; t < 4; t++) {
            dreg[t] = Cf[f * NGEN + lane + 32 * t] - vreg[t];
            pr[t] = f;
        }
        unsigned scan = 0;
        int jmin;
        float mu;

        while (true) {
            unsigned bestk = 0xFFFFFFFFu;
            unsigned bestj = 0xFFFFFFFFu;
            #pragma unroll
            for (int t = 0; t < 4; t++) {
                if (!((scan >> t) & 1u)) {
                    unsigned k = fkey(dreg[t]);
                    if (k < bestk) { bestk = k; bestj = (unsigned)(lane + 32 * t); }
                }
            }
            unsigned kmin = redux_min_u32(bestk);
            unsigned j1   = redux_min_u32((bestk == kmin) ? bestj : 0xFFFFFFFFu);
            mu   = funkey(kmin);
            jmin = (int)j1;

            const int tt = jmin >> 5, sl = jmin & 31;
            if (sl == lane) scan |= 1u << tt;

            int   ysel = (tt == 0) ? yreg[0] : (tt == 1) ? yreg[1]
                       : (tt == 2) ? yreg[2] : yreg[3];
            float vsel = (tt == 0) ? vreg[0] : (tt == 1) ? vreg[1]
                       : (tt == 2) ? vreg[2] : vreg[3];
            int   i1 = __shfl_sync(0xffffffffu, ysel, sl);
            float vj = __shfl_sync(0xffffffffu, vsel, sl);
            if (i1 < 0) break;

            float ui = Cf[i1 * NGEN + jmin] - vj;

            #pragma unroll
            for (int t = 0; t < 4; t++) {
                if (!((scan >> t) & 1u)) {
                    int j = lane + 32 * t;
                    float nd = mu + (Cf[i1 * NGEN + j] - vreg[t]) - ui;
                    if (nd < dreg[t]) { dreg[t] = nd; pr[t] = i1; }
                }
            }
        }

        // deferred potential update over scanned columns
        #pragma unroll
        for (int t = 0; t < 4; t++)
            if ((scan >> t) & 1u) vreg[t] += dreg[t] - mu;

        // augment along pred chain
        int j = jmin;
        while (true) {
            const int tt = j >> 5, sl = j & 31;
            int psel = (tt == 0) ? pr[0] : (tt == 1) ? pr[1]
                     : (tt == 2) ? pr[2] : pr[3];
            int i = __shfl_sync(0xffffffffu, psel, sl);
            if ((j & 31) == lane) yreg[j >> 5] = i;   // y[j] = i
            int jn = 0;
            if (lane == 0) {
                jn = (i == f) ? -1 : x[i];
                x[i] = j;
            }
            jn = __shfl_sync(0xffffffffu, jn, 0);
            if (i == f) break;
            j = jn;
        }
        __syncwarp();
    }

    // transposed return: col[i] = x[i]; order = argsort(col)
    if (lane < G) {
        int c = x[lane];
        int rank = 0;
        #pragma unroll
        for (int r2 = 0; r2 < G; r2++) rank += (x[r2] < c) ? 1 : 0;
        rows_out[b * G + rank] = (float)c;
        cols_out[b * G + rank] = (float)lane;
    }
}

// ---------------------------------------------------------------------------
// Launch
// ---------------------------------------------------------------------------
extern "C" void kernel_launch(void* const* d_in, const int* in_sizes, int n_in,
                              void* d_out, int out_size) {
    const float* prel = (const float*)d_in[0];
    Ptrs ptrs;
    for (int d = 0; d < 8; d++) ptrs.pos[d]  = (const float*)d_in[1 + d];
    const int* grel = (const int*)d_in[9];
    for (int d = 0; d < 8; d++) ptrs.gidx[d] = (const int*)d_in[10 + d];

    float* out = (float*)d_out;

    cost_kernel<<<BSZ * NGEN, 256>>>(prel, grel, ptrs, out);

    float* rows_out = out + COST_ELEMS;
    float* cols_out = rows_out + (size_t)BSZ * G;
    lsa_kernel<<<BSZ, 32>>>(out, rows_out, cols_out);
}

// round 9
// speedup vs baseline: 1.3132x; 1.0229x over previous
#include <cuda_runtime.h>
#include <math_constants.h>

#define BSZ   64
#define NGEN  128
#define NCLS  30
#define SEQ   2048
#define G     16
#define TGOLD (BSZ * G)                              // 1024
#define COST_ELEMS ((size_t)BSZ * NGEN * TGOLD)      // 8388608
#define NITER 16                                     // 8 dists x 2 rows

struct Ptrs {
    const float* pos[8];   // 8 positional logit tensors [BSZ*NGEN, SEQ]
    const int*   gidx[8];  // 8 gold index arrays [TGOLD]
};

// ---------------------------------------------------------------------------
// cp.async helpers
// ---------------------------------------------------------------------------
__device__ __forceinline__ unsigned smem_u32(const void* p) {
    unsigned a;
    asm("{ .reg .u64 t; cvta.to.shared.u64 t, %1; cvt.u32.u64 %0, t; }"
        : "=r"(a) : "l"(p));
    return a;
}
__device__ __forceinline__ void cp_async16(unsigned dst, const float* src) {
    asm volatile("cp.async.cg.shared.global [%0], [%1], 16;" :: "r"(dst), "l"(src));
}

// ---------------------------------------------------------------------------
// Cost kernel: one block per TWO (b,n) rows, 256 threads.
// Iteration k = (dist d = k>>1, row r = k&1): gold-index int4 loaded once per
// dist (r==0) and reused for r==1 -> index L2 traffic halved. Depth-3
// cp.async pipeline over 4 raw-logit stages; exp at use site (no probs STS);
// ONE __syncthreads per iteration. Arithmetic identical (bit-identical out).
// ---------------------------------------------------------------------------
__global__ __launch_bounds__(256)
void cost_kernel(const float* __restrict__ prel, const int* __restrict__ grel,
                 Ptrs ptrs, float* __restrict__ out) {
    const int row0 = blockIdx.x * 2;
    const int tid  = threadIdx.x;
    const int w    = tid >> 5;
    const int lane = tid & 31;

    __shared__ float stage[4][SEQ];       // 32 KB (raw logits)
    __shared__ float relp[2][32];
    __shared__ float red[2][8];

    const unsigned sbase = smem_u32(&stage[0][0]);

    // prologue: iterations 0..2 = (d0,r0),(d0,r1),(d1,r0)
    #pragma unroll
    for (int k = 0; k < 3; k++) {
        const float* src = ptrs.pos[k >> 1] + (size_t)(row0 + (k & 1)) * SEQ;
        unsigned dst = sbase + (unsigned)((k & 3) * (SEQ * 4)) + (unsigned)(tid * 16);
        cp_async16(dst, src + 4 * tid);
        cp_async16(dst + 4096, src + 1024 + 4 * tid);
        asm volatile("cp.async.commit_group;");
    }

    // rel-class softmax: warp 0 -> row0, warp 1 -> row0+1 (overlaps loads)
    if (tid < 64) {
        float e = (lane < NCLS) ? __expf(prel[(size_t)(row0 + w) * NCLS + lane]) : 0.f;
        float s = e;
        #pragma unroll
        for (int o = 16; o; o >>= 1) s += __shfl_xor_sync(0xffffffffu, s, o);
        if (lane < NCLS) relp[w][lane] = e / s;
    }
    __syncthreads();

    const int4 gr = ((const int4*)grel)[tid];
    float acc[2][4];
    #pragma unroll
    for (int r = 0; r < 2; r++) {
        acc[r][0] = relp[r][gr.x];
        acc[r][1] = relp[r][gr.y];
        acc[r][2] = relp[r][gr.z];
        acc[r][3] = relp[r][gr.w];
    }

    int4 gi;
    #pragma unroll
    for (int k = 0; k < NITER; k++) {
        const int d  = k >> 1;
        const int r  = k & 1;
        const int sb = k & 3;
        const int pb = k & 1;

        // wait for MY copies of iteration k (up to 2 later groups in flight)
        if (k <= 13)      asm volatile("cp.async.wait_group 2;");
        else if (k == 14) asm volatile("cp.async.wait_group 1;");
        else              asm volatile("cp.async.wait_group 0;");

        // gather indices: load once per dist, reuse for the second row
        if (r == 0) gi = ((const int4*)ptrs.gidx[d])[tid];

        // sum of exps over this thread's own staged elements (raw kept)
        const float4* sp = (const float4*)&stage[sb][0];
        float4 x0 = sp[tid];
        float4 x1 = sp[tid + 256];
        float lsum = (__expf(x0.x) + __expf(x0.y)) + (__expf(x0.z) + __expf(x0.w))
                   + (__expf(x1.x) + __expf(x1.y)) + (__expf(x1.z) + __expf(x1.w));
        #pragma unroll
        for (int o = 16; o; o >>= 1) lsum += __shfl_xor_sync(0xffffffffu, lsum, o);
        if (lane == 0) red[pb][w] = lsum;
        __syncthreads();     // (a) red visible (b) all cp.asyncs of iter k
                             // published (c) gathers of k-1 ordered before
                             // the k+3 refill below (same stage slot)

        float s = ((red[pb][0] + red[pb][1]) + (red[pb][2] + red[pb][3]))
                + ((red[pb][4] + red[pb][5]) + (red[pb][6] + red[pb][7]));
        float inv = 1.0f / s;

        acc[r][0] += __expf(stage[sb][gi.x]) * inv;
        acc[r][1] += __expf(stage[sb][gi.y]) * inv;
        acc[r][2] += __expf(stage[sb][gi.z]) * inv;
        acc[r][3] += __expf(stage[sb][gi.w]) * inv;

        // refill: iteration k+3 into stage (k+3)&3
        if (k + 3 < NITER) {
            const int kn = k + 3;
            const float* src = ptrs.pos[kn >> 1] + (size_t)(row0 + (kn & 1)) * SEQ;
            unsigned dst = sbase + (unsigned)((kn & 3) * (SEQ * 4))
                                 + (unsigned)(tid * 16);
            cp_async16(dst, src + 4 * tid);
            cp_async16(dst + 4096, src + 1024 + 4 * tid);
            asm volatile("cp.async.commit_group;");
        }
    }

    #pragma unroll
    for (int r = 0; r < 2; r++) {
        float4 res = make_float4(-acc[r][0], -acc[r][1], -acc[r][2], -acc[r][3]);
        ((float4*)(out + (size_t)(row0 + r) * TGOLD))[tid] = res;
    }
}

// ---------------------------------------------------------------------------
// f32 monotone key + redux.min
// ---------------------------------------------------------------------------
__device__ __forceinline__ unsigned fkey(float x) {
    int b = __float_as_int(x);
    return (unsigned)(b ^ ((b >> 31) | 0x80000000));
}
__device__ __forceinline__ float funkey(unsigned k) {
    int b = (k & 0x80000000u) ? (int)(k ^ 0x80000000u) : (int)(~k);
    return __int_as_float(b);
}
__device__ __forceinline__ unsigned redux_min_u32(unsigned x) {
    unsigned r;
    asm volatile("redux.sync.min.u32 %0, %1, 0xffffffff;" : "=r"(r) : "r"(x));
    return r;
}

// ---------------------------------------------------------------------------
// LSA: one warp per example. LAPJV, f32, register-resident state.
// NEW: greedy initialization — row-reduction u_i = min_j C[i][j] with v = 0
// (rectangular dual feasibility + CS hold exactly), sequential greedy
// assignment of free argmin columns. ~15/16 rows assigned greedily; only
// collided rows run the Dijkstra phase. Final matching = unique LP optimum.
// C[i][j] = cost[b, j, b*G + i]  (16 x 128 transposed view).
// ---------------------------------------------------------------------------
__global__ __launch_bounds__(32)
void lsa_kernel(const float* __restrict__ cost, float* __restrict__ rows_out,
                float* __restrict__ cols_out) {
    const int b = blockIdx.x;
    const int lane = threadIdx.x;

    __shared__ float Cf[G * NGEN];   // 8 KB
    __shared__ int   x[G];           // row -> col

    for (int j = lane; j < NGEN; j += 32) {
        const float4* src = (const float4*)(cost + ((size_t)(b * NGEN + j)) * TGOLD + b * G);
        #pragma unroll
        for (int q = 0; q < 4; q++) {
            float4 f = src[q];
            Cf[(q * 4 + 0) * NGEN + j] = f.x;
            Cf[(q * 4 + 1) * NGEN + j] = f.y;
            Cf[(q * 4 + 2) * NGEN + j] = f.z;
            Cf[(q * 4 + 3) * NGEN + j] = f.w;
        }
    }
    __syncwarp();

    float vreg[4];                 // v[j], j = lane + 32*t (ZERO, stays <= 0)
    int   yreg[4];                 // col -> row (-1 free)
    #pragma unroll
    for (int t = 0; t < 4; t++) { vreg[t] = 0.f; yreg[t] = -1; }

    // ---- greedy init: u_i = min_j C[i][j]; assign if argmin column free ----
    unsigned assigned = 0;         // uniform across lanes
    for (int i = 0; i < G; i++) {
        unsigned bestk = 0xFFFFFFFFu, bestj = 0xFFFFFFFFu;
        #pragma unroll
        for (int t = 0; t < 4; t++) {
            unsigned k = fkey(Cf[i * NGEN + lane + 32 * t]);
            if (k < bestk) { bestk = k; bestj = (unsigned)(lane + 32 * t); }
        }
        unsigned kmin = redux_min_u32(bestk);
        unsigned j1   = redux_min_u32((bestk == kmin) ? bestj : 0xFFFFFFFFu);
        const int tt = (int)j1 >> 5, sl = (int)j1 & 31;
        int ysel = (tt == 0) ? yreg[0] : (tt == 1) ? yreg[1]
                 : (tt == 2) ? yreg[2] : yreg[3];
        int yj = __shfl_sync(0xffffffffu, ysel, sl);
        if (yj < 0) {
            if (sl == lane) yreg[tt] = i;
            if (lane == 0) x[i] = (int)j1;
            assigned |= 1u << i;
        }
    }
    __syncwarp();

    // ---- Dijkstra phases only for unassigned rows ----
    for (int f = 0; f < G; f++) {
        if (assigned & (1u << f)) continue;

        float dreg[4];
        int   pr[4];
        #pragma unroll
        for (int t = 0; t < 4; t++) {
            dreg[t] = Cf[f * NGEN + lane + 32 * t] - vreg[t];
            pr[t] = f;
        }
        unsigned scan = 0;
        int jmin;
        float mu;

        while (true) {
            unsigned bestk = 0xFFFFFFFFu;
            unsigned bestj = 0xFFFFFFFFu;
            #pragma unroll
            for (int t = 0; t < 4; t++) {
                if (!((scan >> t) & 1u)) {
                    unsigned k = fkey(dreg[t]);
                    if (k < bestk) { bestk = k; bestj = (unsigned)(lane + 32 * t); }
                }
            }
            unsigned kmin = redux_min_u32(bestk);
            unsigned j1   = redux_min_u32((bestk == kmin) ? bestj : 0xFFFFFFFFu);
            mu   = funkey(kmin);
            jmin = (int)j1;

            const int tt = jmin >> 5, sl = jmin & 31;
            if (sl == lane) scan |= 1u << tt;

            int   ysel = (tt == 0) ? yreg[0] : (tt == 1) ? yreg[1]
                       : (tt == 2) ? yreg[2] : yreg[3];
            float vsel = (tt == 0) ? vreg[0] : (tt == 1) ? vreg[1]
                       : (tt == 2) ? vreg[2] : vreg[3];
            int   i1 = __shfl_sync(0xffffffffu, ysel, sl);
            float vj = __shfl_sync(0xffffffffu, vsel, sl);
            if (i1 < 0) break;

            float ui = Cf[i1 * NGEN + jmin] - vj;   // = u_{i1} by CS

            #pragma unroll
            for (int t = 0; t < 4; t++) {
                if (!((scan >> t) & 1u)) {
                    int j = lane + 32 * t;
                    float nd = mu + (Cf[i1 * NGEN + j] - vreg[t]) - ui;
                    if (nd < dreg[t]) { dreg[t] = nd; pr[t] = i1; }
                }
            }
        }

        // deferred potential update over scanned columns
        #pragma unroll
        for (int t = 0; t < 4; t++)
            if ((scan >> t) & 1u) vreg[t] += dreg[t] - mu;

        // augment along pred chain
        int j = jmin;
        while (true) {
            const int tt = j >> 5, sl = j & 31;
            int psel = (tt == 0) ? pr[0] : (tt == 1) ? pr[1]
                     : (tt == 2) ? pr[2] : pr[3];
            int i = __shfl_sync(0xffffffffu, psel, sl);
            if ((j & 31) == lane) yreg[j >> 5] = i;   // y[j] = i
            int jn = 0;
            if (lane == 0) {
                jn = (i == f) ? -1 : x[i];
                x[i] = j;
            }
            jn = __shfl_sync(0xffffffffu, jn, 0);
            if (i == f) break;
            j = jn;
        }
        __syncwarp();
    }
    __syncwarp();

    // transposed return: col[i] = x[i]; order = argsort(col)
    if (lane < G) {
        int c = x[lane];
        int rank = 0;
        #pragma unroll
        for (int r2 = 0; r2 < G; r2++) rank += (x[r2] < c) ? 1 : 0;
        rows_out[b * G + rank] = (float)c;
        cols_out[b * G + rank] = (float)lane;
    }
}

// ---------------------------------------------------------------------------
// Launch
// ---------------------------------------------------------------------------
extern "C" void kernel_launch(void* const* d_in, const int* in_sizes, int n_in,
                              void* d_out, int out_size) {
    const float* prel = (const float*)d_in[0];
    Ptrs ptrs;
    for (int d = 0; d < 8; d++) ptrs.pos[d]  = (const float*)d_in[1 + d];
    const int* grel = (const int*)d_in[9];
    for (int d = 0; d < 8; d++) ptrs.gidx[d] = (const int*)d_in[10 + d];

    float* out = (float*)d_out;

    cost_kernel<<<(BSZ * NGEN) / 2, 256>>>(prel, grel, ptrs, out);

    float* rows_out = out + COST_ELEMS;
    float* cols_out = rows_out + (size_t)BSZ * G;
    lsa_kernel<<<BSZ, 32>>>(out, rows_out, cols_out);
}